// round 1
// baseline (speedup 1.0000x reference)
#include <cuda_runtime.h>
#include <math.h>

#define LTOK   4096
#define NB     4
#define EDIM   512
#define MSLOT  12
#define DFFDIM 2048
#define NCYC   3
#define SCALE_Q 0.044194173824159216f   // 512^-0.5
#define LNEPS   1e-5f

// ---------------- scratch (static device memory; no allocations) ----------------
__device__ float g_Kp[NB*LTOK*EDIM];      // slot-phase K = q @ sWk^T   [(l*NB+n)][e]
__device__ float g_Vp[NB*LTOK*EDIM];      // slot-phase V = q @ sWv^T
__device__ float g_Vf[NB*LTOK*EDIM];      // final V = v @ Wv^T
__device__ float g_P[NB*LTOK*LTOK];       // [n][l][s] logits -> probs (268 MB)
__device__ float g_slots[NB*MSLOT*EDIM];  // [n][m][e]
__device__ float g_Qs[NB*MSLOT*EDIM];
__device__ float g_att[NB*MSLOT*LTOK];    // [n][m][l]
__device__ float g_attsm[NB*MSLOT*LTOK];
__device__ float g_src[NB*MSLOT*EDIM];
__device__ float g_srcn[NB*MSLOT*EDIM];
__device__ float g_h[NB*MSLOT*DFFDIM];
__device__ float g_f2[NB*MSLOT*EDIM];

// ---------------- generic fp32 SGEMM: C = scale * A * op(B) ----------------
// 128x64 tile, BK=16, 256 threads, 8x4 microtile.
// BTRANS=1: B is [Ncols][K] (torch-style weight, C = A*B^T)
// BTRANS=0: B is [K][Ncols]
template<int BTRANS>
__global__ void sgemm_kernel(const float* __restrict__ A, int lda, long sAz,
                             const float* __restrict__ B, int ldb, long sBz,
                             float* __restrict__ C, int ldc, long sCz,
                             int K, float scale)
{
    __shared__ float As[16][132];   // padded: conflict-light stores, aligned float4 reads
    __shared__ float Bs[16][68];
    A += (long)blockIdx.z * sAz;
    B += (long)blockIdx.z * sBz;
    C += (long)blockIdx.z * sCz;
    int row0 = blockIdx.y * 128, col0 = blockIdx.x * 64;
    int tid = threadIdx.x, tx = tid & 15, ty = tid >> 4;
    float acc[8][4] = {};

    for (int kt = 0; kt < K; kt += 16) {
        #pragma unroll
        for (int i = 0; i < 8; i++) {
            int idx = tid + i * 256; int r = idx >> 4, kk = idx & 15;
            As[kk][r] = A[(long)(row0 + r) * lda + kt + kk];
        }
        if (BTRANS) {
            #pragma unroll
            for (int i = 0; i < 4; i++) {
                int idx = tid + i * 256; int c = idx >> 4, kk = idx & 15;
                Bs[kk][c] = B[(long)(col0 + c) * ldb + kt + kk];
            }
        } else {
            #pragma unroll
            for (int i = 0; i < 4; i++) {
                int idx = tid + i * 256; int c = idx & 63, kk = idx >> 6;
                Bs[kk][c] = B[(long)(kt + kk) * ldb + col0 + c];
            }
        }
        __syncthreads();
        #pragma unroll
        for (int kk = 0; kk < 16; kk++) {
            float4 a0 = *(const float4*)&As[kk][ty * 8];
            float4 a1 = *(const float4*)&As[kk][ty * 8 + 4];
            float4 bb = *(const float4*)&Bs[kk][tx * 4];
            float a[8] = {a0.x, a0.y, a0.z, a0.w, a1.x, a1.y, a1.z, a1.w};
            float b[4] = {bb.x, bb.y, bb.z, bb.w};
            #pragma unroll
            for (int i = 0; i < 8; i++)
                #pragma unroll
                for (int j = 0; j < 4; j++)
                    acc[i][j] += a[i] * b[j];
        }
        __syncthreads();
    }
    #pragma unroll
    for (int i = 0; i < 8; i++)
        #pragma unroll
        for (int j = 0; j < 4; j++)
            C[(long)(row0 + ty * 8 + i) * ldc + col0 + tx * 4 + j] = acc[i][j] * scale;
}

// ---------------- logits GEMM with token_assign epilogue ----------------
// P[n][l][s] = (Q_l . K_s) * (sum_m slot_att[n,l,m] * slot_assign[n,m,s])
__global__ void logits_kernel(const float* __restrict__ Qf, const float* __restrict__ Kf,
                              const float* __restrict__ satt, const float* __restrict__ sassign,
                              float* __restrict__ P)
{
    __shared__ float As[16][132];
    __shared__ float Bs[16][68];
    __shared__ float Ssa[128 * MSLOT];
    __shared__ float Ssg[MSLOT][64];
    int n = blockIdx.z;
    const float* A = Qf + n * EDIM;
    const float* B = Kf + n * EDIM;
    const int lda = NB * EDIM, ldb = NB * EDIM;
    int row0 = blockIdx.y * 128, col0 = blockIdx.x * 64;
    int tid = threadIdx.x, tx = tid & 15, ty = tid >> 4;
    float acc[8][4] = {};

    for (int kt = 0; kt < EDIM; kt += 16) {
        #pragma unroll
        for (int i = 0; i < 8; i++) {
            int idx = tid + i * 256; int r = idx >> 4, kk = idx & 15;
            As[kk][r] = A[(long)(row0 + r) * lda + kt + kk];
        }
        #pragma unroll
        for (int i = 0; i < 4; i++) {
            int idx = tid + i * 256; int c = idx >> 4, kk = idx & 15;
            Bs[kk][c] = B[(long)(col0 + c) * ldb + kt + kk];
        }
        __syncthreads();
        #pragma unroll
        for (int kk = 0; kk < 16; kk++) {
            float4 a0 = *(const float4*)&As[kk][ty * 8];
            float4 a1 = *(const float4*)&As[kk][ty * 8 + 4];
            float4 bb = *(const float4*)&Bs[kk][tx * 4];
            float a[8] = {a0.x, a0.y, a0.z, a0.w, a1.x, a1.y, a1.z, a1.w};
            float b[4] = {bb.x, bb.y, bb.z, bb.w};
            #pragma unroll
            for (int i = 0; i < 8; i++)
                #pragma unroll
                for (int j = 0; j < 4; j++)
                    acc[i][j] += a[i] * b[j];
        }
        __syncthreads();
    }
    // epilogue: rank-12 token_assign
    const float* sa = satt + (long)(n * LTOK + row0) * MSLOT;   // contiguous 128*12
    #pragma unroll
    for (int i = 0; i < 6; i++) Ssa[tid + i * 256] = sa[tid + i * 256];
    #pragma unroll
    for (int i = 0; i < 3; i++) {
        int idx = tid + i * 256; int m = idx >> 6, c = idx & 63;
        Ssg[m][c] = sassign[(long)(n * MSLOT + m) * LTOK + col0 + c];
    }
    __syncthreads();
    #pragma unroll
    for (int i = 0; i < 8; i++) {
        int r = ty * 8 + i;
        #pragma unroll
        for (int j = 0; j < 4; j++) {
            int c = tx * 4 + j;
            float t = 0.f;
            #pragma unroll
            for (int m = 0; m < MSLOT; m++) t += Ssa[r * MSLOT + m] * Ssg[m][c];
            P[(long)n * LTOK * LTOK + (long)(row0 + r) * LTOK + col0 + c] = acc[i][j] * t;
        }
    }
}

// ---------------- softmax over rows of width 4096 ----------------
__global__ void softmax_rows_kernel(const float* __restrict__ In, float* __restrict__ Out)
{
    __shared__ float buf[LTOK];
    __shared__ float red[256];
    long base = (long)blockIdx.x * LTOK;
    int tid = threadIdx.x;
    float mx = -3.4e38f;
    for (int i = tid; i < LTOK; i += 256) { float v = In[base + i]; buf[i] = v; mx = fmaxf(mx, v); }
    red[tid] = mx; __syncthreads();
    for (int st = 128; st > 0; st >>= 1) { if (tid < st) red[tid] = fmaxf(red[tid], red[tid + st]); __syncthreads(); }
    mx = red[0]; __syncthreads();
    float s = 0.f;
    for (int i = tid; i < LTOK; i += 256) { float e = expf(buf[i] - mx); buf[i] = e; s += e; }
    red[tid] = s; __syncthreads();
    for (int st = 128; st > 0; st >>= 1) { if (tid < st) red[tid] += red[tid + st]; __syncthreads(); }
    float inv = 1.f / red[0];
    for (int i = tid; i < LTOK; i += 256) Out[base + i] = buf[i] * inv;
}

// ---------------- small row-GEMM: out[r][o] = f(sum_k X[r][k]*W[o][k]) ----------------
// mode 0: *scale; mode 1: +bias then exact gelu; mode 2: +bias
__global__ void small_gemm_kernel(const float* __restrict__ X, int K,
                                  const float* __restrict__ W,
                                  const float* __restrict__ bias,
                                  float* __restrict__ Out, int ldo,
                                  int mode, float scale)
{
    __shared__ float xs[DFFDIM];
    int r = blockIdx.x, tid = threadIdx.x;
    for (int i = tid; i < K; i += 128) xs[i] = X[(long)r * K + i];
    __syncthreads();
    int o = blockIdx.y * 128 + tid;
    const float4* w4 = (const float4*)(W + (long)o * K);
    const float4* x4 = (const float4*)xs;
    float acc = 0.f;
    for (int k = 0; k < K / 4; k++) {
        float4 w = w4[k], x = x4[k];
        acc += w.x * x.x + w.y * x.y + w.z * x.z + w.w * x.w;
    }
    float v;
    if (mode == 0) v = acc * scale;
    else if (mode == 1) { float t = acc + bias[o]; v = 0.5f * t * (1.0f + erff(t * 0.70710678118654752f)); }
    else v = acc + bias[o];
    Out[(long)r * ldo + o] = v;
}

// ---------------- slot-phase kernels ----------------
__global__ void init_slots_kernel(const float* __restrict__ sv)
{
    int idx = blockIdx.x * 256 + threadIdx.x;
    if (idx < NB * MSLOT * EDIM) {
        int e = idx % EDIM; int nm = idx / EDIM; int m = nm % MSLOT; int n = nm / MSLOT;
        g_slots[idx] = sv[(m * NB + n) * EDIM + e];   // slot_vectors [M,N,E] -> [n][m][e]
    }
}

__global__ void copy_kernel(float* __restrict__ dst, const float* __restrict__ src, int cnt)
{
    int idx = blockIdx.x * 256 + threadIdx.x;
    if (idx < cnt) dst[idx] = src[idx];
}

__global__ void slots_out_kernel(float* __restrict__ out)
{
    int idx = blockIdx.x * 256 + threadIdx.x;
    if (idx < NB * MSLOT * EDIM) {
        int e = idx % EDIM; int nm = idx / EDIM; int m = nm % MSLOT; int n = nm / MSLOT;
        out[(m * NB + n) * EDIM + e] = g_slots[idx];   // -> [M,N,E]
    }
}

// att[n][m][l] = Qs[n][m] . Kp[l,n]
__global__ void slot_att_kernel()
{
    int n = blockIdx.x;
    int l = blockIdx.y * 128 + threadIdx.x;
    __shared__ float Qsm[MSLOT * EDIM];
    const float* src = g_Qs + n * MSLOT * EDIM;
    for (int i = threadIdx.x; i < MSLOT * EDIM; i += 128) Qsm[i] = src[i];
    __syncthreads();
    const float4* kr = (const float4*)(g_Kp + (long)(l * NB + n) * EDIM);
    float acc[MSLOT] = {};
    for (int e4 = 0; e4 < EDIM / 4; e4++) {
        float4 kv = kr[e4];
        #pragma unroll
        for (int m = 0; m < MSLOT; m++) {
            float4 q = *(const float4*)&Qsm[m * EDIM + e4 * 4];
            acc[m] += q.x * kv.x + q.y * kv.y + q.z * kv.z + q.w * kv.w;
        }
    }
    #pragma unroll
    for (int m = 0; m < MSLOT; m++) g_att[(long)(n * MSLOT + m) * LTOK + l] = acc[m];
}

// slot_assign[n][m][l] = softmax_m(att) — written straight to d_out (last cycle only)
__global__ void slot_assign_kernel(float* __restrict__ outp)
{
    int n = blockIdx.x;
    int l = blockIdx.y * 256 + threadIdx.x;
    float v[MSLOT]; float mx = -3.4e38f;
    #pragma unroll
    for (int m = 0; m < MSLOT; m++) { v[m] = g_att[(long)(n * MSLOT + m) * LTOK + l]; mx = fmaxf(mx, v[m]); }
    float s = 0.f;
    #pragma unroll
    for (int m = 0; m < MSLOT; m++) { v[m] = expf(v[m] - mx); s += v[m]; }
    float inv = 1.f / s;
    #pragma unroll
    for (int m = 0; m < MSLOT; m++) outp[(long)(n * MSLOT + m) * LTOK + l] = v[m] * inv;
}

// g_src (pre-initialized to slots) += attsm @ Vp ; split over L with atomics
__global__ void slot_update_kernel()
{
    int n = blockIdx.x;
    int e = blockIdx.y * 128 + threadIdx.x;
    int lchunk = blockIdx.z;          // 8 chunks of 512
    __shared__ float w[MSLOT][128];
    float acc[MSLOT] = {};
    for (int l0 = lchunk * 512; l0 < lchunk * 512 + 512; l0 += 128) {
        #pragma unroll
        for (int m = 0; m < MSLOT; m++) w[m][threadIdx.x] = g_attsm[(long)(n * MSLOT + m) * LTOK + l0 + threadIdx.x];
        __syncthreads();
        for (int lt = 0; lt < 128; lt++) {
            float v = g_Vp[(long)((l0 + lt) * NB + n) * EDIM + e];
            #pragma unroll
            for (int m = 0; m < MSLOT; m++) acc[m] += w[m][lt] * v;
        }
        __syncthreads();
    }
    #pragma unroll
    for (int m = 0; m < MSLOT; m++) atomicAdd(&g_src[(n * MSLOT + m) * EDIM + e], acc[m]);
}

__global__ void layernorm_kernel(const float* __restrict__ X, const float* __restrict__ Add,
                                 float* __restrict__ Out,
                                 const float* __restrict__ gg, const float* __restrict__ bb)
{
    int r = blockIdx.x, tid = threadIdx.x;
    __shared__ float xs[EDIM];
    __shared__ float red[256];
    for (int i = tid; i < EDIM; i += 256) {
        float v = X[r * EDIM + i];
        if (Add) v += Add[r * EDIM + i];
        xs[i] = v;
    }
    __syncthreads();
    float s = 0.f;
    for (int i = tid; i < EDIM; i += 256) s += xs[i];
    red[tid] = s; __syncthreads();
    for (int st = 128; st > 0; st >>= 1) { if (tid < st) red[tid] += red[tid + st]; __syncthreads(); }
    float mean = red[0] / EDIM;
    __syncthreads();
    float sq = 0.f;
    for (int i = tid; i < EDIM; i += 256) { float d = xs[i] - mean; sq += d * d; }
    red[tid] = sq; __syncthreads();
    for (int st = 128; st > 0; st >>= 1) { if (tid < st) red[tid] += red[tid + st]; __syncthreads(); }
    float rstd = rsqrtf(red[0] / EDIM + LNEPS);
    for (int i = tid; i < EDIM; i += 256)
        Out[r * EDIM + i] = (xs[i] - mean) * rstd * gg[i] + bb[i];
}

// slot_att[n][l][m] = softmax_m(Qf[l,n] . slots[n][m]) — straight to d_out
__global__ void slot_att_final_kernel(const float* __restrict__ Qf, float* __restrict__ outp)
{
    int n = blockIdx.x;
    int l = blockIdx.y * 128 + threadIdx.x;
    __shared__ float S[MSLOT * EDIM];
    const float* sp = g_slots + n * MSLOT * EDIM;
    for (int i = threadIdx.x; i < MSLOT * EDIM; i += 128) S[i] = sp[i];
    __syncthreads();
    const float4* q4 = (const float4*)(Qf + (long)(l * NB + n) * EDIM);
    float acc[MSLOT] = {};
    for (int e4 = 0; e4 < EDIM / 4; e4++) {
        float4 q = q4[e4];
        #pragma unroll
        for (int m = 0; m < MSLOT; m++) {
            float4 sv = *(const float4*)&S[m * EDIM + e4 * 4];
            acc[m] += sv.x * q.x + sv.y * q.y + sv.z * q.z + sv.w * q.w;
        }
    }
    float mx = -3.4e38f;
    #pragma unroll
    for (int m = 0; m < MSLOT; m++) mx = fmaxf(mx, acc[m]);
    float s = 0.f;
    #pragma unroll
    for (int m = 0; m < MSLOT; m++) { acc[m] = expf(acc[m] - mx); s += acc[m]; }
    float inv = 1.f / s;
    #pragma unroll
    for (int m = 0; m < MSLOT; m++) outp[(long)(n * LTOK + l) * MSLOT + m] = acc[m] * inv;
}

// ---------------- host launcher ----------------
extern "C" void kernel_launch(void* const* d_in, const int* in_sizes, int n_in,
                              void* d_out, int out_size)
{
    const float* queries = (const float*)d_in[0];
    const float* keys    = (const float*)d_in[1];
    const float* values  = (const float*)d_in[2];
    const float* slot_v  = (const float*)d_in[3];
    const float* sWq = (const float*)d_in[4];
    const float* sWk = (const float*)d_in[5];
    const float* sWv = (const float*)d_in[6];
    const float* Wq  = (const float*)d_in[7];
    const float* Wk  = (const float*)d_in[8];
    const float* Wv  = (const float*)d_in[9];
    const float* l1_w = (const float*)d_in[10];
    const float* l1_b = (const float*)d_in[11];
    const float* l2_w = (const float*)d_in[12];
    const float* l2_b = (const float*)d_in[13];
    const float* n1_g = (const float*)d_in[14];
    const float* n1_b = (const float*)d_in[15];
    const float* n2_g = (const float*)d_in[16];
    const float* n2_b = (const float*)d_in[17];
    float* out = (float*)d_out;

    float *Kp, *Vp, *Vf, *P, *slots, *Qs, *att, *attsm, *src, *srcn, *hbuf, *f2;
    cudaGetSymbolAddress((void**)&Kp,    g_Kp);
    cudaGetSymbolAddress((void**)&Vp,    g_Vp);
    cudaGetSymbolAddress((void**)&Vf,    g_Vf);
    cudaGetSymbolAddress((void**)&P,     g_P);
    cudaGetSymbolAddress((void**)&slots, g_slots);
    cudaGetSymbolAddress((void**)&Qs,    g_Qs);
    cudaGetSymbolAddress((void**)&att,   g_att);
    cudaGetSymbolAddress((void**)&attsm, g_attsm);
    cudaGetSymbolAddress((void**)&src,   g_src);
    cudaGetSymbolAddress((void**)&srcn,  g_srcn);
    cudaGetSymbolAddress((void**)&hbuf,  g_h);
    cudaGetSymbolAddress((void**)&f2,    g_f2);

    const int o_Q       = LTOK * NB * EDIM;         // 8388608
    const int o_K       = 2 * o_Q;
    const int o_slots   = 3 * o_Q;                  // 25165824
    const int o_sassign = o_slots + MSLOT * NB * EDIM;
    const int o_satt    = o_sassign + NB * MSLOT * LTOK;

    dim3 gProj(EDIM / 64, (LTOK * NB) / 128, 1);

    // loop-invariant slot-phase projections (tokens = queries)
    sgemm_kernel<1><<<gProj, 256>>>(queries, EDIM, 0, sWk, EDIM, 0, Kp, EDIM, 0, EDIM, 1.0f);
    sgemm_kernel<1><<<gProj, 256>>>(queries, EDIM, 0, sWv, EDIM, 0, Vp, EDIM, 0, EDIM, 1.0f);
    init_slots_kernel<<<96, 256>>>(slot_v);

    for (int c = 0; c < NCYC; c++) {
        // Qs = slots @ sWq^T * SCALING
        small_gemm_kernel<<<dim3(NB * MSLOT, EDIM / 128), 128>>>(slots, EDIM, sWq, nullptr, Qs, EDIM, 0, SCALE_Q);
        slot_att_kernel<<<dim3(NB, LTOK / 128), 128>>>();
        softmax_rows_kernel<<<NB * MSLOT, 256>>>(att, attsm);   // softmax over tokens
        if (c == NCYC - 1)
            slot_assign_kernel<<<dim3(NB, LTOK / 256), 256>>>(out + o_sassign);
        copy_kernel<<<96, 256>>>(src, slots, NB * MSLOT * EDIM);
        slot_update_kernel<<<dim3(NB, EDIM / 128, 8), 128>>>();
        layernorm_kernel<<<NB * MSLOT, 256>>>(src, nullptr, srcn, n1_g, n1_b);
        small_gemm_kernel<<<dim3(NB * MSLOT, DFFDIM / 128), 128>>>(srcn, EDIM, l1_w, l1_b, hbuf, DFFDIM, 1, 1.0f);
        small_gemm_kernel<<<dim3(NB * MSLOT, EDIM / 128), 128>>>(hbuf, DFFDIM, l2_w, l2_b, f2, EDIM, 2, 1.0f);
        layernorm_kernel<<<NB * MSLOT, 256>>>(srcn, f2, slots, n2_g, n2_b);
    }

    slots_out_kernel<<<96, 256>>>(out + o_slots);

    // final projections
    sgemm_kernel<1><<<gProj, 256>>>(queries, EDIM, 0, Wq, EDIM, 0, out + o_Q, EDIM, 0, EDIM, SCALE_Q);
    sgemm_kernel<1><<<gProj, 256>>>(keys,    EDIM, 0, Wk, EDIM, 0, out + o_K, EDIM, 0, EDIM, 1.0f);
    sgemm_kernel<1><<<gProj, 256>>>(values,  EDIM, 0, Wv, EDIM, 0, Vf,        EDIM, 0, EDIM, 1.0f);

    slot_att_final_kernel<<<dim3(NB, LTOK / 128), 128>>>(out + o_Q, out + o_satt);

    // P = (Q K^T) * token_assign  -> softmax -> out = P V
    logits_kernel<<<dim3(LTOK / 64, LTOK / 128, NB), 256>>>(out + o_Q, out + o_K,
                                                            out + o_satt, out + o_sassign, P);
    softmax_rows_kernel<<<NB * LTOK, 256>>>(P, P);
    sgemm_kernel<0><<<dim3(EDIM / 64, LTOK / 128, NB), 256>>>(
        P, LTOK, (long)LTOK * LTOK,
        Vf, NB * EDIM, (long)EDIM,
        out, NB * EDIM, (long)EDIM,
        LTOK, 1.0f);
}

// round 2
// speedup vs baseline: 2.1297x; 2.1297x over previous
#include <cuda_runtime.h>
#include <math.h>

#define LTOK   4096
#define NB     4
#define EDIM   512
#define MSLOT  12
#define DFFDIM 2048
#define NCYC   3
#define SCALE_Q 0.044194173824159216f   // 512^-0.5
#define LNEPS   1e-5f

// ---------------- scratch (static device memory; no allocations) ----------------
__device__ float g_Kp[NB*LTOK*EDIM];      // slot-phase K = q @ sWk^T   [(l*NB+n)][e]
__device__ float g_Vp[NB*LTOK*EDIM];      // slot-phase V = q @ sWv^T
__device__ float g_Vf[NB*LTOK*EDIM];      // final V = v @ Wv^T
__device__ float g_P[NB*LTOK*LTOK];       // [n][l][s] logits -> probs (268 MB)
__device__ float g_slots[NB*MSLOT*EDIM];  // [n][m][e]
__device__ float g_Qs[NB*MSLOT*EDIM];
__device__ float g_att[NB*MSLOT*LTOK];    // [n][m][l]
__device__ float g_attsm[NB*MSLOT*LTOK];
__device__ float g_src[NB*MSLOT*EDIM];
__device__ float g_srcn[NB*MSLOT*EDIM];
__device__ float g_h[NB*MSLOT*DFFDIM];
__device__ float g_f2[NB*MSLOT*EDIM];

// ---------------- tf32 tensor-core GEMM ----------------
__device__ __forceinline__ unsigned f2tf(float f) {
    unsigned u; asm("cvt.rna.tf32.f32 %0, %1;" : "=r"(u) : "f"(f)); return u;
}

// C = scale * A * op(B)   (block 128x128, k-tile 32, 8 warps, warp tile 64x32)
// BTRANS=1: B is [N][K] row-major (C = A*B^T).  BTRANS=0: B is [K][N].
// EPI=1: logits epilogue — C *= token_assign (rank-12 from satt/sassign).
template<int BTRANS, int EPI>
__global__ void __launch_bounds__(256, 2)
mma_gemm_kernel(const float* __restrict__ A, int lda, long sAz,
                const float* __restrict__ B, int ldb, long sBz,
                float* __restrict__ C, int ldc, long sCz,
                int K, float scale,
                const float* __restrict__ satt, const float* __restrict__ sassign)
{
    __shared__ unsigned As[128 * 36];          // [row][k], pitch 36 (bank-clean)
    __shared__ unsigned Bs[128 * 36];          // NT: [col][k] p36 ; NN: [k][n] p136
    int z = blockIdx.z;
    A += (long)z * sAz; B += (long)z * sBz; C += (long)z * sCz;
    int row0 = blockIdx.y * 128, col0 = blockIdx.x * 128;
    int tid = threadIdx.x, lane = tid & 31, warp = tid >> 5;
    int wm = warp >> 2, wn = warp & 3;         // 2 x 4 warps
    int gid = lane >> 2, tig = lane & 3;
    float acc[4][4][4] = {};

    int ra = tid >> 3, ka = (tid & 7) << 2;
    for (int kt = 0; kt < K; kt += 32) {
        #pragma unroll
        for (int i = 0; i < 4; i++) {
            int r = ra + 32 * i;
            float4 v = *(const float4*)&A[(long)(row0 + r) * lda + kt + ka];
            uint4 u = { f2tf(v.x), f2tf(v.y), f2tf(v.z), f2tf(v.w) };
            *(uint4*)&As[r * 36 + ka] = u;
        }
        if (BTRANS) {
            #pragma unroll
            for (int i = 0; i < 4; i++) {
                int r = ra + 32 * i;
                float4 v = *(const float4*)&B[(long)(col0 + r) * ldb + kt + ka];
                uint4 u = { f2tf(v.x), f2tf(v.y), f2tf(v.z), f2tf(v.w) };
                *(uint4*)&Bs[r * 36 + ka] = u;
            }
        } else {
            #pragma unroll
            for (int i = 0; i < 4; i++) {
                int k = (tid >> 5) + 8 * i;
                int nc = (tid & 31) << 2;
                float4 v = *(const float4*)&B[(long)(kt + k) * ldb + col0 + nc];
                uint4 u = { f2tf(v.x), f2tf(v.y), f2tf(v.z), f2tf(v.w) };
                *(uint4*)&Bs[k * 136 + nc] = u;
            }
        }
        __syncthreads();
        #pragma unroll
        for (int ks = 0; ks < 4; ks++) {
            int k0 = ks * 8;
            unsigned a[4][4], b[4][2];
            #pragma unroll
            for (int mt = 0; mt < 4; mt++) {
                int r = wm * 64 + mt * 16 + gid;
                a[mt][0] = As[r * 36 + k0 + tig];
                a[mt][1] = As[(r + 8) * 36 + k0 + tig];
                a[mt][2] = As[r * 36 + k0 + tig + 4];
                a[mt][3] = As[(r + 8) * 36 + k0 + tig + 4];
            }
            #pragma unroll
            for (int nt = 0; nt < 4; nt++) {
                int c = wn * 32 + nt * 8 + gid;
                if (BTRANS) {
                    b[nt][0] = Bs[c * 36 + k0 + tig];
                    b[nt][1] = Bs[c * 36 + k0 + tig + 4];
                } else {
                    b[nt][0] = Bs[(k0 + tig) * 136 + c];
                    b[nt][1] = Bs[(k0 + tig + 4) * 136 + c];
                }
            }
            #pragma unroll
            for (int mt = 0; mt < 4; mt++)
                #pragma unroll
                for (int nt = 0; nt < 4; nt++)
                    asm volatile(
                        "mma.sync.aligned.m16n8k8.row.col.f32.tf32.tf32.f32 "
                        "{%0,%1,%2,%3}, {%4,%5,%6,%7}, {%8,%9}, {%0,%1,%2,%3};\n"
                        : "+f"(acc[mt][nt][0]), "+f"(acc[mt][nt][1]),
                          "+f"(acc[mt][nt][2]), "+f"(acc[mt][nt][3])
                        : "r"(a[mt][0]), "r"(a[mt][1]), "r"(a[mt][2]), "r"(a[mt][3]),
                          "r"(b[nt][0]), "r"(b[nt][1]));
        }
        __syncthreads();
    }

    // ---- epilogue ----
    float* Ssa = (float*)As;            // reuse smem: 128x12 slot_att rows
    float* Ssg = (float*)As + 1536;     // 12x128 slot_assign cols
    if (EPI) {
        const float* sa = satt + ((long)z * LTOK + row0) * MSLOT;
        #pragma unroll
        for (int i = 0; i < 6; i++) Ssa[tid + i * 256] = sa[tid + i * 256];
        #pragma unroll
        for (int i = 0; i < 6; i++) {
            int idx = tid + i * 256;    // m = idx>>7, c = idx&127
            Ssg[idx] = sassign[((long)z * MSLOT + (idx >> 7)) * LTOK + col0 + (idx & 127)];
        }
        __syncthreads();
    }
    #pragma unroll
    for (int mt = 0; mt < 4; mt++) {
        int r0l = wm * 64 + mt * 16 + gid;
        int r1l = r0l + 8;
        #pragma unroll
        for (int nt = 0; nt < 4; nt++) {
            int c0l = wn * 32 + nt * 8 + 2 * tig;
            float m00 = scale, m01 = scale, m10 = scale, m11 = scale;
            if (EPI) {
                float t00 = 0.f, t01 = 0.f, t10 = 0.f, t11 = 0.f;
                #pragma unroll
                for (int m = 0; m < MSLOT; m++) {
                    float sa0 = Ssa[r0l * MSLOT + m], sa1 = Ssa[r1l * MSLOT + m];
                    float sg0 = Ssg[m * 128 + c0l],   sg1 = Ssg[m * 128 + c0l + 1];
                    t00 += sa0 * sg0; t01 += sa0 * sg1;
                    t10 += sa1 * sg0; t11 += sa1 * sg1;
                }
                m00 = t00; m01 = t01; m10 = t10; m11 = t11;
            }
            float2 o0 = { acc[mt][nt][0] * m00, acc[mt][nt][1] * m01 };
            float2 o1 = { acc[mt][nt][2] * m10, acc[mt][nt][3] * m11 };
            *(float2*)&C[(long)(row0 + r0l) * ldc + col0 + c0l] = o0;
            *(float2*)&C[(long)(row0 + r1l) * ldc + col0 + c0l] = o1;
        }
    }
}

// ---------------- softmax over rows of width 4096 ----------------
__global__ void softmax_rows_kernel(const float* __restrict__ In, float* __restrict__ Out)
{
    __shared__ float buf[LTOK];
    __shared__ float red[256];
    long base = (long)blockIdx.x * LTOK;
    int tid = threadIdx.x;
    float mx = -3.4e38f;
    for (int i = tid; i < LTOK; i += 256) { float v = In[base + i]; buf[i] = v; mx = fmaxf(mx, v); }
    red[tid] = mx; __syncthreads();
    for (int st = 128; st > 0; st >>= 1) { if (tid < st) red[tid] = fmaxf(red[tid], red[tid + st]); __syncthreads(); }
    mx = red[0]; __syncthreads();
    float s = 0.f;
    for (int i = tid; i < LTOK; i += 256) { float e = expf(buf[i] - mx); buf[i] = e; s += e; }
    red[tid] = s; __syncthreads();
    for (int st = 128; st > 0; st >>= 1) { if (tid < st) red[tid] += red[tid + st]; __syncthreads(); }
    float inv = 1.f / red[0];
    for (int i = tid; i < LTOK; i += 256) Out[base + i] = buf[i] * inv;
}

// ---------------- small row-GEMM (slot FFN etc.) ----------------
__global__ void small_gemm_kernel(const float* __restrict__ X, int K,
                                  const float* __restrict__ W,
                                  const float* __restrict__ bias,
                                  float* __restrict__ Out, int ldo,
                                  int mode, float scale)
{
    __shared__ float xs[DFFDIM];
    int r = blockIdx.x, tid = threadIdx.x;
    for (int i = tid; i < K; i += 128) xs[i] = X[(long)r * K + i];
    __syncthreads();
    int o = blockIdx.y * 128 + tid;
    const float4* w4 = (const float4*)(W + (long)o * K);
    const float4* x4 = (const float4*)xs;
    float acc = 0.f;
    for (int k = 0; k < K / 4; k++) {
        float4 w = w4[k], x = x4[k];
        acc += w.x * x.x + w.y * x.y + w.z * x.z + w.w * x.w;
    }
    float v;
    if (mode == 0) v = acc * scale;
    else if (mode == 1) { float t = acc + bias[o]; v = 0.5f * t * (1.0f + erff(t * 0.70710678118654752f)); }
    else v = acc + bias[o];
    Out[(long)r * ldo + o] = v;
}

// ---------------- slot-phase kernels ----------------
__global__ void init_slots_kernel(const float* __restrict__ sv)
{
    int idx = blockIdx.x * 256 + threadIdx.x;
    if (idx < NB * MSLOT * EDIM) {
        int e = idx % EDIM; int nm = idx / EDIM; int m = nm % MSLOT; int n = nm / MSLOT;
        g_slots[idx] = sv[(m * NB + n) * EDIM + e];
    }
}

__global__ void copy_kernel(float* __restrict__ dst, const float* __restrict__ src, int cnt)
{
    int idx = blockIdx.x * 256 + threadIdx.x;
    if (idx < cnt) dst[idx] = src[idx];
}

__global__ void slots_out_kernel(float* __restrict__ out)
{
    int idx = blockIdx.x * 256 + threadIdx.x;
    if (idx < NB * MSLOT * EDIM) {
        int e = idx % EDIM; int nm = idx / EDIM; int m = nm % MSLOT; int n = nm / MSLOT;
        out[(m * NB + n) * EDIM + e] = g_slots[idx];
    }
}

// att[n][m][l] = Qs[n][m] . Kp[l,n]
__global__ void slot_att_kernel()
{
    int n = blockIdx.x;
    int l = blockIdx.y * 128 + threadIdx.x;
    __shared__ float Qsm[MSLOT * EDIM];
    const float* src = g_Qs + n * MSLOT * EDIM;
    for (int i = threadIdx.x; i < MSLOT * EDIM; i += 128) Qsm[i] = src[i];
    __syncthreads();
    const float4* kr = (const float4*)(g_Kp + (long)(l * NB + n) * EDIM);
    float acc[MSLOT] = {};
    for (int e4 = 0; e4 < EDIM / 4; e4++) {
        float4 kv = kr[e4];
        #pragma unroll
        for (int m = 0; m < MSLOT; m++) {
            float4 q = *(const float4*)&Qsm[m * EDIM + e4 * 4];
            acc[m] += q.x * kv.x + q.y * kv.y + q.z * kv.z + q.w * kv.w;
        }
    }
    #pragma unroll
    for (int m = 0; m < MSLOT; m++) g_att[(long)(n * MSLOT + m) * LTOK + l] = acc[m];
}

__global__ void slot_assign_kernel(float* __restrict__ outp)
{
    int n = blockIdx.x;
    int l = blockIdx.y * 256 + threadIdx.x;
    float v[MSLOT]; float mx = -3.4e38f;
    #pragma unroll
    for (int m = 0; m < MSLOT; m++) { v[m] = g_att[(long)(n * MSLOT + m) * LTOK + l]; mx = fmaxf(mx, v[m]); }
    float s = 0.f;
    #pragma unroll
    for (int m = 0; m < MSLOT; m++) { v[m] = expf(v[m] - mx); s += v[m]; }
    float inv = 1.f / s;
    #pragma unroll
    for (int m = 0; m < MSLOT; m++) outp[(long)(n * MSLOT + m) * LTOK + l] = v[m] * inv;
}

// g_src (pre-initialized to slots) += attsm @ Vp ; split over L with atomics
__global__ void slot_update_kernel()
{
    int n = blockIdx.x;
    int e = blockIdx.y * 128 + threadIdx.x;
    int lchunk = blockIdx.z;
    __shared__ float w[MSLOT][128];
    float acc[MSLOT] = {};
    for (int l0 = lchunk * 512; l0 < lchunk * 512 + 512; l0 += 128) {
        #pragma unroll
        for (int m = 0; m < MSLOT; m++) w[m][threadIdx.x] = g_attsm[(long)(n * MSLOT + m) * LTOK + l0 + threadIdx.x];
        __syncthreads();
        for (int lt = 0; lt < 128; lt++) {
            float v = g_Vp[(long)((l0 + lt) * NB + n) * EDIM + e];
            #pragma unroll
            for (int m = 0; m < MSLOT; m++) acc[m] += w[m][lt] * v;
        }
        __syncthreads();
    }
    #pragma unroll
    for (int m = 0; m < MSLOT; m++) atomicAdd(&g_src[(n * MSLOT + m) * EDIM + e], acc[m]);
}

__global__ void layernorm_kernel(const float* __restrict__ X, const float* __restrict__ Add,
                                 float* __restrict__ Out,
                                 const float* __restrict__ gg, const float* __restrict__ bb)
{
    int r = blockIdx.x, tid = threadIdx.x;
    __shared__ float xs[EDIM];
    __shared__ float red[256];
    for (int i = tid; i < EDIM; i += 256) {
        float v = X[r * EDIM + i];
        if (Add) v += Add[r * EDIM + i];
        xs[i] = v;
    }
    __syncthreads();
    float s = 0.f;
    for (int i = tid; i < EDIM; i += 256) s += xs[i];
    red[tid] = s; __syncthreads();
    for (int st = 128; st > 0; st >>= 1) { if (tid < st) red[tid] += red[tid + st]; __syncthreads(); }
    float mean = red[0] / EDIM;
    __syncthreads();
    float sq = 0.f;
    for (int i = tid; i < EDIM; i += 256) { float d = xs[i] - mean; sq += d * d; }
    red[tid] = sq; __syncthreads();
    for (int st = 128; st > 0; st >>= 1) { if (tid < st) red[tid] += red[tid + st]; __syncthreads(); }
    float rstd = rsqrtf(red[0] / EDIM + LNEPS);
    for (int i = tid; i < EDIM; i += 256)
        Out[r * EDIM + i] = (xs[i] - mean) * rstd * gg[i] + bb[i];
}

// slot_att[n][l][m] = softmax_m(Qf[l,n] . slots[n][m]) — straight to d_out
__global__ void slot_att_final_kernel(const float* __restrict__ Qf, float* __restrict__ outp)
{
    int n = blockIdx.x;
    int l = blockIdx.y * 128 + threadIdx.x;
    __shared__ float S[MSLOT * EDIM];
    const float* sp = g_slots + n * MSLOT * EDIM;
    for (int i = threadIdx.x; i < MSLOT * EDIM; i += 128) S[i] = sp[i];
    __syncthreads();
    const float4* q4 = (const float4*)(Qf + (long)(l * NB + n) * EDIM);
    float acc[MSLOT] = {};
    for (int e4 = 0; e4 < EDIM / 4; e4++) {
        float4 q = q4[e4];
        #pragma unroll
        for (int m = 0; m < MSLOT; m++) {
            float4 sv = *(const float4*)&S[m * EDIM + e4 * 4];
            acc[m] += sv.x * q.x + sv.y * q.y + sv.z * q.z + sv.w * q.w;
        }
    }
    float mx = -3.4e38f;
    #pragma unroll
    for (int m = 0; m < MSLOT; m++) mx = fmaxf(mx, acc[m]);
    float s = 0.f;
    #pragma unroll
    for (int m = 0; m < MSLOT; m++) { acc[m] = expf(acc[m] - mx); s += acc[m]; }
    float inv = 1.f / s;
    #pragma unroll
    for (int m = 0; m < MSLOT; m++) outp[(long)(n * LTOK + l) * MSLOT + m] = acc[m] * inv;
}

// ---------------- host launcher ----------------
extern "C" void kernel_launch(void* const* d_in, const int* in_sizes, int n_in,
                              void* d_out, int out_size)
{
    const float* queries = (const float*)d_in[0];
    const float* keys    = (const float*)d_in[1];
    const float* values  = (const float*)d_in[2];
    const float* slot_v  = (const float*)d_in[3];
    const float* sWq = (const float*)d_in[4];
    const float* sWk = (const float*)d_in[5];
    const float* sWv = (const float*)d_in[6];
    const float* Wq  = (const float*)d_in[7];
    const float* Wk  = (const float*)d_in[8];
    const float* Wv  = (const float*)d_in[9];
    const float* l1_w = (const float*)d_in[10];
    const float* l1_b = (const float*)d_in[11];
    const float* l2_w = (const float*)d_in[12];
    const float* l2_b = (const float*)d_in[13];
    const float* n1_g = (const float*)d_in[14];
    const float* n1_b = (const float*)d_in[15];
    const float* n2_g = (const float*)d_in[16];
    const float* n2_b = (const float*)d_in[17];
    float* out = (float*)d_out;

    float *Kp, *Vp, *Vf, *P, *slots, *Qs, *att, *attsm, *src, *srcn, *hbuf, *f2;
    cudaGetSymbolAddress((void**)&Kp,    g_Kp);
    cudaGetSymbolAddress((void**)&Vp,    g_Vp);
    cudaGetSymbolAddress((void**)&Vf,    g_Vf);
    cudaGetSymbolAddress((void**)&P,     g_P);
    cudaGetSymbolAddress((void**)&slots, g_slots);
    cudaGetSymbolAddress((void**)&Qs,    g_Qs);
    cudaGetSymbolAddress((void**)&att,   g_att);
    cudaGetSymbolAddress((void**)&attsm, g_attsm);
    cudaGetSymbolAddress((void**)&src,   g_src);
    cudaGetSymbolAddress((void**)&srcn,  g_srcn);
    cudaGetSymbolAddress((void**)&hbuf,  g_h);
    cudaGetSymbolAddress((void**)&f2,    g_f2);

    const int o_Q       = LTOK * NB * EDIM;         // 8388608
    const int o_K       = 2 * o_Q;
    const int o_slots   = 3 * o_Q;                  // 25165824
    const int o_sassign = o_slots + MSLOT * NB * EDIM;
    const int o_satt    = o_sassign + NB * MSLOT * LTOK;

    dim3 gProj(EDIM / 128, (LTOK * NB) / 128, 1);   // (4, 128)

    // loop-invariant slot-phase projections (tokens = queries)
    mma_gemm_kernel<1,0><<<gProj, 256>>>(queries, EDIM, 0, sWk, EDIM, 0, Kp, EDIM, 0, EDIM, 1.0f, nullptr, nullptr);
    mma_gemm_kernel<1,0><<<gProj, 256>>>(queries, EDIM, 0, sWv, EDIM, 0, Vp, EDIM, 0, EDIM, 1.0f, nullptr, nullptr);
    init_slots_kernel<<<96, 256>>>(slot_v);

    for (int c = 0; c < NCYC; c++) {
        small_gemm_kernel<<<dim3(NB * MSLOT, EDIM / 128), 128>>>(slots, EDIM, sWq, nullptr, Qs, EDIM, 0, SCALE_Q);
        slot_att_kernel<<<dim3(NB, LTOK / 128), 128>>>();
        softmax_rows_kernel<<<NB * MSLOT, 256>>>(att, attsm);
        if (c == NCYC - 1)
            slot_assign_kernel<<<dim3(NB, LTOK / 256), 256>>>(out + o_sassign);
        copy_kernel<<<96, 256>>>(src, slots, NB * MSLOT * EDIM);
        slot_update_kernel<<<dim3(NB, EDIM / 128, 8), 128>>>();
        layernorm_kernel<<<NB * MSLOT, 256>>>(src, nullptr, srcn, n1_g, n1_b);
        small_gemm_kernel<<<dim3(NB * MSLOT, DFFDIM / 128), 128>>>(srcn, EDIM, l1_w, l1_b, hbuf, DFFDIM, 1, 1.0f);
        small_gemm_kernel<<<dim3(NB * MSLOT, EDIM / 128), 128>>>(hbuf, DFFDIM, l2_w, l2_b, f2, EDIM, 2, 1.0f);
        layernorm_kernel<<<NB * MSLOT, 256>>>(srcn, f2, slots, n2_g, n2_b);
    }

    slots_out_kernel<<<96, 256>>>(out + o_slots);

    // final projections
    mma_gemm_kernel<1,0><<<gProj, 256>>>(queries, EDIM, 0, Wq, EDIM, 0, out + o_Q, EDIM, 0, EDIM, SCALE_Q, nullptr, nullptr);
    mma_gemm_kernel<1,0><<<gProj, 256>>>(keys,    EDIM, 0, Wk, EDIM, 0, out + o_K, EDIM, 0, EDIM, 1.0f, nullptr, nullptr);
    mma_gemm_kernel<1,0><<<gProj, 256>>>(values,  EDIM, 0, Wv, EDIM, 0, Vf,        EDIM, 0, EDIM, 1.0f, nullptr, nullptr);

    slot_att_final_kernel<<<dim3(NB, LTOK / 128), 128>>>(out + o_Q, out + o_satt);

    // P = (Q K^T) * token_assign  -> softmax -> out = P V
    mma_gemm_kernel<1,1><<<dim3(LTOK / 128, LTOK / 128, NB), 256>>>(
        out + o_Q, NB * EDIM, EDIM,
        out + o_K, NB * EDIM, EDIM,
        P, LTOK, (long)LTOK * LTOK,
        EDIM, 1.0f, out + o_satt, out + o_sassign);
    softmax_rows_kernel<<<NB * LTOK, 256>>>(P, P);
    mma_gemm_kernel<0,0><<<dim3(EDIM / 128, LTOK / 128, NB), 256>>>(
        P, LTOK, (long)LTOK * LTOK,
        Vf, NB * EDIM, EDIM,
        out, NB * EDIM, EDIM,
        LTOK, 1.0f, nullptr, nullptr);
}